// round 15
// baseline (speedup 1.0000x reference)
#include <cuda_runtime.h>
#include <cstdint>
#include <math.h>

#define BATCH  4
#define SEQ    2048
#define DMODEL 1024
#define DK     64

// Q/K: tf32 bits, Q pre-scaled 0.125, d-columns pair-permuted (j<4 -> 2j else 2(j-4)+1).
__device__ unsigned g_proj[2][BATCH * SEQ * DK];
// V: pair-packed rows (r, r+4): word = rp*128 + 2*((c + 4*(r&3))&63) + ((r>>2)&1),
//    rp = (r>>3)*4 + (r&3).   [BATCH*SEQ/2][128] words.
__device__ unsigned g_v2[(BATCH * SEQ / 2) * 128];
// W: pair-packed rows (k, k+4), same scheme. [3][512][128] words.
__device__ unsigned g_w2[3][512 * 128];

extern __shared__ unsigned dyn_smem[];

// ---- helpers ---------------------------------------------------------------
__device__ __forceinline__ unsigned f2tf(float x) {
    unsigned u;
    asm("cvt.rna.tf32.f32 %0, %1;" : "=r"(u) : "f"(x));
    return u;
}

__device__ __forceinline__ void mma8(float4& d,
                                     unsigned a0, unsigned a1, unsigned a2, unsigned a3,
                                     unsigned b0, unsigned b1) {
    asm("mma.sync.aligned.m16n8k8.row.col.f32.tf32.tf32.f32 "
        "{%0,%1,%2,%3},{%4,%5,%6,%7},{%8,%9},{%0,%1,%2,%3};"
        : "+f"(d.x), "+f"(d.y), "+f"(d.z), "+f"(d.w)
        : "r"(a0), "r"(a1), "r"(a2), "r"(a3), "r"(b0), "r"(b1));
}

__device__ __forceinline__ uint32_t smem_u32(const void* p) {
    return (uint32_t)__cvta_generic_to_shared(p);
}
__device__ __forceinline__ void cp_async16(uint32_t dst, const void* src) {
    asm volatile("cp.async.cg.shared.global [%0], [%1], 16;" :: "r"(dst), "l"(src) : "memory");
}
__device__ __forceinline__ void cp_commit() {
    asm volatile("cp.async.commit_group;" ::: "memory");
}
__device__ __forceinline__ void cp_wait0() {
    asm volatile("cp.async.wait_group 0;" ::: "memory");
}

// ===========================================================================
// wprep: W f32 [k][n] -> pair-packed tf32.  grid (64,1,3), 256 thr.
// ===========================================================================
__global__ __launch_bounds__(256) void wprep_kernel(
    const float* __restrict__ w0, const float* __restrict__ w1, const float* __restrict__ w2)
{
    const int sel = blockIdx.z;
    const float* __restrict__ W = (sel == 0) ? w0 : (sel == 1) ? w1 : w2;
    unsigned* __restrict__ O = g_w2[sel];

    int idx4 = blockIdx.x * 256 + threadIdx.x;   // 0..16383
    int k  = idx4 >> 4;
    int n4 = (idx4 & 15) * 4;
    float4 wv = *(const float4*)(W + (size_t)k * DK + n4);
    int kp   = ((k >> 3) << 2) | (k & 3);
    int slot = (k >> 2) & 1;
    int rot  = 4 * (k & 3);
    unsigned v[4] = {f2tf(wv.x), f2tf(wv.y), f2tf(wv.z), f2tf(wv.w)};
#pragma unroll
    for (int j = 0; j < 4; ++j) {
        int colp = (n4 + j + rot) & 63;
        O[kp * 128 + 2 * colp + slot] = v[j];
    }
}

// ===========================================================================
// Projection: Y = tf32(X @ W + b); Q scaled 0.125; Q/K col-pair-permuted;
// V pair-packed to g_v2.  grid (64,1,3), 256 thr, CTA 128 rows, K chunks 64.
// 2 CTAs/SM (smem 102.4KB, regs capped via launch_bounds(256,2)).
// ===========================================================================
#define XS 68   // Xs stride: a-frag bank = 4g+m, conflict-free (LDS.32)

__global__ __launch_bounds__(256, 2) void proj_kernel(
    const float* __restrict__ x0, const float* __restrict__ x1, const float* __restrict__ x2,
    const float* __restrict__ b0v, const float* __restrict__ b1v, const float* __restrict__ b2v)
{
    unsigned* Xs = dyn_smem;                 // 2 * 128*68 = 17408 words
    unsigned* Ws = dyn_smem + 2 * 128 * XS;  // 2 * 4096  =  8192 words
    const uint32_t ws_u32 = smem_u32(Ws);

    const int sel = blockIdx.z;
    const float* __restrict__ X  = (sel == 0) ? x0 : (sel == 1) ? x1 : x2;
    const float* __restrict__ Bb = (sel == 0) ? b0v : (sel == 1) ? b1v : b2v;
    const unsigned* __restrict__ Wt2 = g_w2[sel];
    const float oscale = (sel == 0) ? 0.125f : 1.0f;

    const int tid  = threadIdx.x;
    const int lane = tid & 31;
    const int g    = lane >> 2;
    const int m    = lane & 3;
    const int wid  = tid >> 5;
    const int wr   = wid & 3;      // row group (32 rows)
    const int wc   = wid >> 2;     // col group (32 cols)
    const int row0 = blockIdx.x * 128;

    const int lr = tid >> 4;
    const int lc = (tid & 15) * 4;

    float4 acc[2][4];
#pragma unroll
    for (int h = 0; h < 2; ++h)
#pragma unroll
        for (int n = 0; n < 4; ++n) acc[h][n] = make_float4(0.f, 0.f, 0.f, 0.f);

    // ---- prefetch chunk 0 ----
    float4 xr[8];
#pragma unroll
    for (int p = 0; p < 8; ++p) {
        int r = lr + p * 16;
        xr[p] = *(const float4*)(X + (size_t)(row0 + r) * DMODEL + lc);
    }
#pragma unroll
    for (int p = 0; p < 4; ++p) {
        int idx = tid + p * 256;             // 0..1023 uint4 chunks of W tile
        cp_async16(ws_u32 + (uint32_t)(idx * 4) * 4, Wt2 + idx * 4);
    }
    cp_commit();
#pragma unroll
    for (int p = 0; p < 8; ++p) {
        int r = lr + p * 16;
        *(uint4*)&Xs[r * XS + lc] =
            make_uint4(f2tf(xr[p].x), f2tf(xr[p].y), f2tf(xr[p].z), f2tf(xr[p].w));
    }
    cp_wait0();
    __syncthreads();

    const int cb = 32 * wc + g + 4 * m;      // rotated base col for W b-frags

    int cur = 0;
    for (int c = 0; c < 16; ++c) {
        const unsigned* Xc = Xs + cur * 128 * XS;
        const unsigned* Wc = Ws + cur * 4096;
        const int nxt = cur ^ 1;
        const bool has_next = (c + 1 < 16);

        if (has_next) {
            const int k0 = (c + 1) * 64;
#pragma unroll
            for (int p = 0; p < 8; ++p) {
                int r = lr + p * 16;
                xr[p] = *(const float4*)(X + (size_t)(row0 + r) * DMODEL + k0 + lc);
            }
#pragma unroll
            for (int p = 0; p < 4; ++p) {
                int idx = tid + p * 256;
                cp_async16(ws_u32 + (uint32_t)(nxt * 4096 + idx * 4) * 4,
                           Wt2 + (c + 1) * 4096 + idx * 4);
            }
            cp_commit();
        }

        // compute: 8 k-steps x 2 row halves x 4 n-tiles
#pragma unroll
        for (int kk = 0; kk < 8; ++kk) {
            const unsigned* Wrow = Wc + (kk * 4 + m) * 128;
            uint2 wb[4];
#pragma unroll
            for (int n = 0; n < 4; ++n) {
                int colp = (cb + 8 * n) & 63;
                wb[n] = *(const uint2*)&Wrow[2 * colp];
            }
#pragma unroll
            for (int h = 0; h < 2; ++h) {
                int r = 32 * wr + 16 * h + g;
                unsigned a0 = Xc[r * XS + kk * 8 + m];
                unsigned a1 = Xc[(r + 8) * XS + kk * 8 + m];
                unsigned a2 = Xc[r * XS + kk * 8 + m + 4];
                unsigned a3 = Xc[(r + 8) * XS + kk * 8 + m + 4];
#pragma unroll
                for (int n = 0; n < 4; ++n)
                    mma8(acc[h][n], a0, a1, a2, a3, wb[n].x, wb[n].y);
            }
        }

        if (has_next) {
            unsigned* Xn = Xs + nxt * 128 * XS;
#pragma unroll
            for (int p = 0; p < 8; ++p) {
                int r = lr + p * 16;
                *(uint4*)&Xn[r * XS + lc] =
                    make_uint4(f2tf(xr[p].x), f2tf(xr[p].y), f2tf(xr[p].z), f2tf(xr[p].w));
            }
        }
        cp_wait0();
        __syncthreads();
        cur = nxt;
    }

    // epilogue
#pragma unroll
    for (int h = 0; h < 2; ++h) {
#pragma unroll
        for (int n = 0; n < 4; ++n) {
            int col = 32 * wc + n * 8 + 2 * m;
            float bj0 = Bb[col];
            float bj1 = Bb[col + 1];
            int r = row0 + 32 * wr + 16 * h + g;
            unsigned o00 = f2tf((acc[h][n].x + bj0) * oscale);
            unsigned o01 = f2tf((acc[h][n].y + bj1) * oscale);
            unsigned o10 = f2tf((acc[h][n].z + bj0) * oscale);
            unsigned o11 = f2tf((acc[h][n].w + bj1) * oscale);
            if (sel == 2) {
#pragma unroll
                for (int e = 0; e < 4; ++e) {
                    int R  = (e & 2) ? (r + 8) : r;
                    int cc = col + (e & 1);
                    unsigned val = (e == 0) ? o00 : (e == 1) ? o01 : (e == 2) ? o10 : o11;
                    int rp   = ((R >> 3) << 2) | (R & 3);
                    int slot = (R >> 2) & 1;
                    int colp = (cc + 4 * (R & 3)) & 63;
                    g_v2[rp * 128 + 2 * colp + slot] = val;
                }
            } else {
                unsigned* __restrict__ Y = g_proj[sel];
                int base = 32 * wc + n * 8;
                int pos0 = (m < 2) ? 4 * m : 4 * m - 7;   // col-pair perm of j=2m
                Y[(size_t)r * DK + base + pos0]           = o00;
                Y[(size_t)r * DK + base + pos0 + 2]       = o01;
                Y[(size_t)(r + 8) * DK + base + pos0]     = o10;
                Y[(size_t)(r + 8) * DK + base + pos0 + 2] = o11;
            }
        }
    }
}

// ===========================================================================
// Fused attention: 128-key tiles, KSS=72 (conflict-free LDS.64 K/Q frags),
// V pair-packed.  cp.async, double-buffered, 512 thr.
// ===========================================================================
#define KSS 72   // start bank = (8g+2m) mod 32: bijective per 16-lane phase

__global__ __launch_bounds__(512, 1) void attn_kernel(float* __restrict__ out)
{
    unsigned* Ks = dyn_smem;                   // 2 * 128*72 = 18432 words
    unsigned* Vs = dyn_smem + 2 * 128 * KSS;   // 2 * 8192  = 16384 words
    float* den = (float*)(dyn_smem + 2 * 128 * KSS + 2 * 8192);
    float* Of0 = (float*)Ks;                   // 4096 <= 18432
    float* Of1 = (float*)Vs;                   // 4096 <= 16384
    const uint32_t ks_u32 = smem_u32(Ks);
    const uint32_t vs_u32 = smem_u32(Vs);

    const int tid  = threadIdx.x;
    const int wid  = tid >> 5;
    const int lane = tid & 31;
    const int g    = lane >> 2;
    const int m    = lane & 3;
    const int wr   = wid & 3;      // q-row group (16 rows)
    const int wkc  = wid >> 2;     // key group (32 keys)

    const int b  = blockIdx.y;
    const int q0 = blockIdx.x * 64;

    const unsigned* __restrict__ Qg = g_proj[0] + ((size_t)b * SEQ + q0) * DK;
    const unsigned* __restrict__ Kg = g_proj[1] + (size_t)b * SEQ * DK;

    const int lr = tid >> 4;        // 0..31
    const int lc = (tid & 15) * 4;

    if (tid < 64) den[tid] = 0.f;

    // ---- stage Q (64 rows) through Ks buffer 0 ----
#pragma unroll
    for (int p = 0; p < 2; ++p) {
        int r = lr + p * 32;
        *(uint4*)&Ks[r * KSS + lc] = *(const uint4*)(Qg + (size_t)r * DK + lc);
    }
    __syncthreads();

    unsigned qa[8][4];
#pragma unroll
    for (int kk = 0; kk < 8; ++kk) {
        int r = 16 * wr + g;
        uint2 qlo = *(const uint2*)&Ks[r * KSS + kk * 8 + 2 * m];
        uint2 qhi = *(const uint2*)&Ks[(r + 8) * KSS + kk * 8 + 2 * m];
        qa[kk][0] = qlo.x;
        qa[kk][2] = qlo.y;
        qa[kk][1] = qhi.x;
        qa[kk][3] = qhi.y;
    }
    __syncthreads();

    float4 oacc[8];
#pragma unroll
    for (int n = 0; n < 8; ++n) {
        oacc[n] = make_float4(0.f, 0.f, 0.f, 0.f);
    }
    float dp0 = 0.f;
    float dp1 = 0.f;

    const int s0 = (lane & ~3) | (m >> 1);
    const int s1 = s0 + 2;
    const bool od = (m & 1);

    // ---- preload key tile 0 (128 keys) ----
#pragma unroll
    for (int p = 0; p < 4; ++p) {
        int r = lr + p * 32;
        cp_async16(ks_u32 + (uint32_t)(r * KSS + lc) * 4, Kg + (size_t)r * DK + lc);
    }
    {
        const unsigned* Vsrc = g_v2 + ((size_t)b * (SEQ / 2)) * 128;
#pragma unroll
        for (int p = 0; p < 4; ++p) {
            int idx = tid + p * 512;            // 0..2047 uint4 chunks
            cp_async16(vs_u32 + (uint32_t)(idx * 4) * 4, Vsrc + idx * 4);
        }
    }
    cp_commit();

    const int vcb = g + 4 * m;

    int cur = 0;
    for (int t = 0; t < SEQ / 128; ++t) {
        cp_wait0();
        __syncthreads();

        const unsigned* Kc = Ks + cur * 128 * KSS;
        const unsigned* Vc = Vs + cur * 8192;
        const int nxt = cur ^ 1;

        if (t + 1 < SEQ / 128) {
            int n1 = (t + 1) * 128;
#pragma unroll
            for (int p = 0; p < 4; ++p) {
                int r = lr + p * 32;
                cp_async16(ks_u32 + (uint32_t)(nxt * 128 * KSS + r * KSS + lc) * 4,
                           Kg + (size_t)(n1 + r) * DK + lc);
            }
            const unsigned* Vsrc = g_v2 + ((size_t)b * (SEQ / 2) + (size_t)(t + 1) * 64) * 128;
#pragma unroll
            for (int p = 0; p < 4; ++p) {
                int idx = tid + p * 512;
                cp_async16(vs_u32 + (uint32_t)(nxt * 8192 + idx * 4) * 4, Vsrc + idx * 4);
            }
            cp_commit();
        }

        // ---- S = Q K^T  (warp: 16 rows x 32 keys) ----
        float4 sa[4];
#pragma unroll
        for (int n = 0; n < 4; ++n) sa[n] = make_float4(0.f, 0.f, 0.f, 0.f);
#pragma unroll
        for (int kk = 0; kk < 8; ++kk) {
#pragma unroll
            for (int n = 0; n < 4; ++n) {
                int krow = 32 * wkc + n * 8 + g;
                uint2 kb = *(const uint2*)&Kc[krow * KSS + kk * 8 + 2 * m];
                mma8(sa[n], qa[kk][0], qa[kk][1], qa[kk][2], qa[kk][3], kb.x, kb.y);
            }
        }

        // ---- exp ----
#pragma unroll
        for (int n = 0; n < 4; ++n) {
            float e0 = __uint_as_float(f2tf(__expf(sa[n].x)));
            float e1 = __uint_as_float(f2tf(__expf(sa[n].y)));
            float e2 = __uint_as_float(f2tf(__expf(sa[n].z)));
            float e3 = __uint_as_float(f2tf(__expf(sa[n].w)));
            dp0 += e0 + e1;
            dp1 += e2 + e3;
            sa[n] = make_float4(e0, e1, e2, e3);
        }

        // ---- O += E V ----
#pragma unroll
        for (int kk2 = 0; kk2 < 4; ++kk2) {
            float c0 = sa[kk2].x;
            float c1 = sa[kk2].y;
            float c2 = sa[kk2].z;
            float c3 = sa[kk2].w;
            float x00 = __shfl_sync(0xffffffffu, c0, s0);
            float x01 = __shfl_sync(0xffffffffu, c1, s0);
            float x10 = __shfl_sync(0xffffffffu, c2, s0);
            float x11 = __shfl_sync(0xffffffffu, c3, s0);
            float x20 = __shfl_sync(0xffffffffu, c0, s1);
            float x21 = __shfl_sync(0xffffffffu, c1, s1);
            float x30 = __shfl_sync(0xffffffffu, c2, s1);
            float x31 = __shfl_sync(0xffffffffu, c3, s1);
            unsigned a0 = __float_as_uint(od ? x01 : x00);
            unsigned a1 = __float_as_uint(od ? x11 : x10);
            unsigned a2 = __float_as_uint(od ? x21 : x20);
            unsigned a3 = __float_as_uint(od ? x31 : x30);
            const unsigned* Vrow = Vc + ((4 * wkc + kk2) * 4 + m) * 128;
#pragma unroll
            for (int n2 = 0; n2 < 8; ++n2) {
                int colp = (vcb + 8 * n2) & 63;
                uint2 vb = *(const uint2*)&Vrow[2 * colp];
                mma8(oacc[n2], a0, a1, a2, a3, vb.x, vb.y);
            }
        }

        cur = nxt;
    }
    __syncthreads();

    // ---- denominator ----
    dp0 += __shfl_xor_sync(0xffffffffu, dp0, 1);
    dp0 += __shfl_xor_sync(0xffffffffu, dp0, 2);
    dp1 += __shfl_xor_sync(0xffffffffu, dp1, 1);
    dp1 += __shfl_xor_sync(0xffffffffu, dp1, 2);
    if (m == 0) {
        atomicAdd(&den[16 * wr + g], dp0);
        atomicAdd(&den[16 * wr + g + 8], dp1);
    }

    // ---- O reduction ----
    if (wkc == 0) {
#pragma unroll
        for (int n2 = 0; n2 < 8; ++n2) {
            int r = 16 * wr + g;
            int col = n2 * 8 + 2 * m;
            *(float2*)&Of0[r * 64 + col]       = make_float2(oacc[n2].x, oacc[n2].y);
            *(float2*)&Of0[(r + 8) * 64 + col] = make_float2(oacc[n2].z, oacc[n2].w);
        }
    } else if (wkc == 1) {
#pragma unroll
        for (int n2 = 0; n2 < 8; ++n2) {
            int r = 16 * wr + g;
            int col = n2 * 8 + 2 * m;
            *(float2*)&Of1[r * 64 + col]       = make_float2(oacc[n2].x, oacc[n2].y);
            *(float2*)&Of1[(r + 8) * 64 + col] = make_float2(oacc[n2].z, oacc[n2].w);
        }
    }
    __syncthreads();
    if (wkc == 2) {
#pragma unroll
        for (int n2 = 0; n2 < 8; ++n2) {
            int r = 16 * wr + g;
            int col = n2 * 8 + 2 * m;
            float2 p0 = *(float2*)&Of0[r * 64 + col];
            float2 p1 = *(float2*)&Of0[(r + 8) * 64 + col];
            p0.x += oacc[n2].x; p0.y += oacc[n2].y;
            p1.x += oacc[n2].z; p1.y += oacc[n2].w;
            *(float2*)&Of0[r * 64 + col]       = p0;
            *(float2*)&Of0[(r + 8) * 64 + col] = p1;
        }
    } else if (wkc == 3) {
#pragma unroll
        for (int n2 = 0; n2 < 8; ++n2) {
            int r = 16 * wr + g;
            int col = n2 * 8 + 2 * m;
            float2 p0 = *(float2*)&Of1[r * 64 + col];
            float2 p1 = *(float2*)&Of1[(r + 8) * 64 + col];
            p0.x += oacc[n2].x; p0.y += oacc[n2].y;
            p1.x += oacc[n2].z; p1.y += oacc[n2].w;
            *(float2*)&Of1[r * 64 + col]       = p0;
            *(float2*)&Of1[(r + 8) * 64 + col] = p1;
        }
    }
    __syncthreads();

    // ---- normalize + writeout ----
    float* __restrict__ Og = out + ((size_t)b * SEQ + q0) * DK;
#pragma unroll
    for (int i = 0; i < 2; ++i) {
        int e4 = tid + i * 512;
        int row = e4 >> 4;
        float inv = 1.0f / den[row];
        float4 oa = ((const float4*)Of0)[e4];
        float4 ob = ((const float4*)Of1)[e4];
        float4 o;
        o.x = (oa.x + ob.x) * inv;
        o.y = (oa.y + ob.y) * inv;
        o.z = (oa.z + ob.z) * inv;
        o.w = (oa.w + ob.w) * inv;
        ((float4*)Og)[e4] = o;
    }
}

// ---------------------------------------------------------------------------
extern "C" void kernel_launch(void* const* d_in, const int* in_sizes, int n_in,
                              void* d_out, int out_size)
{
    const float* q  = (const float*)d_in[0];
    const float* k  = (const float*)d_in[1];
    const float* v  = (const float*)d_in[2];
    const float* Wq = (const float*)d_in[3];
    const float* bq = (const float*)d_in[4];
    const float* Wk = (const float*)d_in[5];
    const float* bk = (const float*)d_in[6];
    const float* Wv = (const float*)d_in[7];
    const float* bv = (const float*)d_in[8];
    float* out = (float*)d_out;

    const int psmem = (2 * 128 * XS + 2 * 4096) * 4;           // 102400 B
    const int asmem = (2 * 128 * KSS + 2 * 8192 + 64) * 4;     // 139520 B
    cudaFuncSetAttribute(proj_kernel, cudaFuncAttributeMaxDynamicSharedMemorySize, psmem);
    cudaFuncSetAttribute(attn_kernel, cudaFuncAttributeMaxDynamicSharedMemorySize, asmem);

    dim3 wgrid(64, 1, 3);
    wprep_kernel<<<wgrid, 256>>>(Wq, Wk, Wv);

    dim3 pgrid(BATCH * SEQ / 128, 1, 3);
    proj_kernel<<<pgrid, 256, psmem>>>(q, k, v, bq, bk, bv);

    dim3 agrid(SEQ / 64, BATCH);
    attn_kernel<<<agrid, 512, asmem>>>(out);
}

// round 16
// speedup vs baseline: 1.1279x; 1.1279x over previous
#include <cuda_runtime.h>
#include <cstdint>
#include <math.h>

#define BATCH  4
#define SEQ    2048
#define DMODEL 1024
#define DK     64

// Q/K: tf32 bits, Q pre-scaled 0.125, d-columns pair-permuted (j<4 -> 2j else 2(j-4)+1).
__device__ unsigned g_proj[2][BATCH * SEQ * DK];
// V: pair-packed rows (r, r+4): word = rp*128 + 2*((c + 4*(r&3))&63) + ((r>>2)&1),
//    rp = (r>>3)*4 + (r&3).   [BATCH*SEQ/2][128] words.
__device__ unsigned g_v2[(BATCH * SEQ / 2) * 128];
// W: pair-packed rows (k, k+4), same scheme. [3][512][128] words.
__device__ unsigned g_w2[3][512 * 128];

extern __shared__ unsigned dyn_smem[];

// ---- helpers ---------------------------------------------------------------
__device__ __forceinline__ unsigned f2tf(float x) {
    unsigned u;
    asm("cvt.rna.tf32.f32 %0, %1;" : "=r"(u) : "f"(x));
    return u;
}

__device__ __forceinline__ void mma8(float4& d,
                                     unsigned a0, unsigned a1, unsigned a2, unsigned a3,
                                     unsigned b0, unsigned b1) {
    asm("mma.sync.aligned.m16n8k8.row.col.f32.tf32.tf32.f32 "
        "{%0,%1,%2,%3},{%4,%5,%6,%7},{%8,%9},{%0,%1,%2,%3};"
        : "+f"(d.x), "+f"(d.y), "+f"(d.z), "+f"(d.w)
        : "r"(a0), "r"(a1), "r"(a2), "r"(a3), "r"(b0), "r"(b1));
}

__device__ __forceinline__ uint32_t smem_u32(const void* p) {
    return (uint32_t)__cvta_generic_to_shared(p);
}
__device__ __forceinline__ void cp_async16(uint32_t dst, const void* src) {
    asm volatile("cp.async.cg.shared.global [%0], [%1], 16;" :: "r"(dst), "l"(src) : "memory");
}
__device__ __forceinline__ void cp_commit() {
    asm volatile("cp.async.commit_group;" ::: "memory");
}
__device__ __forceinline__ void cp_wait0() {
    asm volatile("cp.async.wait_group 0;" ::: "memory");
}

// ===========================================================================
// wprep: W f32 [k][n] -> pair-packed tf32.  grid (64,1,3), 256 thr.
// ===========================================================================
__global__ __launch_bounds__(256) void wprep_kernel(
    const float* __restrict__ w0, const float* __restrict__ w1, const float* __restrict__ w2)
{
    const int sel = blockIdx.z;
    const float* __restrict__ W = (sel == 0) ? w0 : (sel == 1) ? w1 : w2;
    unsigned* __restrict__ O = g_w2[sel];

    int idx4 = blockIdx.x * 256 + threadIdx.x;   // 0..16383
    int k  = idx4 >> 4;
    int n4 = (idx4 & 15) * 4;
    float4 wv = *(const float4*)(W + (size_t)k * DK + n4);
    int kp   = ((k >> 3) << 2) | (k & 3);
    int slot = (k >> 2) & 1;
    int rot  = 4 * (k & 3);
    unsigned v[4] = {f2tf(wv.x), f2tf(wv.y), f2tf(wv.z), f2tf(wv.w)};
#pragma unroll
    for (int j = 0; j < 4; ++j) {
        int colp = (n4 + j + rot) & 63;
        O[kp * 128 + 2 * colp + slot] = v[j];
    }
}

// ===========================================================================
// Projection: Y = tf32(X @ W + b); Q scaled 0.125; Q/K col-pair-permuted;
// V written pair-packed to g_v2.  grid (128,1,3), 256 thr, K chunks of 64.
// X: LDG -> cvt -> STS.  W: cp.async of pair-packed tiles (LDS.64 b-frags).
// ===========================================================================
#define XS 68   // Xs stride: a-frag bank = 4g+m, conflict-free

__global__ __launch_bounds__(256) void proj_kernel(
    const float* __restrict__ x0, const float* __restrict__ x1, const float* __restrict__ x2,
    const float* __restrict__ b0v, const float* __restrict__ b1v, const float* __restrict__ b2v)
{
    unsigned* Xs = dyn_smem;               // 2 * 64*68 = 8704 words
    unsigned* Ws = dyn_smem + 2 * 64 * XS; // 2 * 4096 = 8192 words (pair-packed tiles)
    const uint32_t ws_u32 = smem_u32(Ws);

    const int sel = blockIdx.z;
    const float* __restrict__ X  = (sel == 0) ? x0 : (sel == 1) ? x1 : x2;
    const float* __restrict__ Bb = (sel == 0) ? b0v : (sel == 1) ? b1v : b2v;
    const unsigned* __restrict__ Wt2 = g_w2[sel];
    const float oscale = (sel == 0) ? 0.125f : 1.0f;

    const int tid  = threadIdx.x;
    const int lane = tid & 31;
    const int g    = lane >> 2;
    const int m    = lane & 3;
    const int wid  = tid >> 5;
    const int wr   = wid & 3;      // row group (16 rows)
    const int wc   = wid >> 2;     // col group (32 cols)
    const int row0 = blockIdx.x * 64;

    const int lr = tid >> 4;
    const int lc = (tid & 15) * 4;

    float4 acc[4];
#pragma unroll
    for (int n = 0; n < 4; ++n) acc[n] = make_float4(0.f, 0.f, 0.f, 0.f);

    // ---- prefetch chunk 0 ----
    float4 xr[4];
#pragma unroll
    for (int p = 0; p < 4; ++p) {
        int r = lr + p * 16;
        xr[p] = *(const float4*)(X + (size_t)(row0 + r) * DMODEL + lc);
    }
#pragma unroll
    for (int p = 0; p < 4; ++p) {
        int idx = tid + p * 256;             // 0..1023 uint4 chunks
        cp_async16(ws_u32 + (uint32_t)(idx * 4) * 4, Wt2 + idx * 4);
    }
    cp_commit();
#pragma unroll
    for (int p = 0; p < 4; ++p) {
        int r = lr + p * 16;
        *(uint4*)&Xs[r * XS + lc] =
            make_uint4(f2tf(xr[p].x), f2tf(xr[p].y), f2tf(xr[p].z), f2tf(xr[p].w));
    }
    cp_wait0();
    __syncthreads();

    const int cb = 32 * wc + g + 4 * m;      // rotated base col for b-frags

    int cur = 0;
    for (int c = 0; c < 16; ++c) {
        const unsigned* Xc = Xs + cur * 64 * XS;
        const unsigned* Wc = Ws + cur * 4096;
        const int nxt = cur ^ 1;
        const bool has_next = (c + 1 < 16);

        if (has_next) {
            const int k0 = (c + 1) * 64;
#pragma unroll
            for (int p = 0; p < 4; ++p) {
                int r = lr + p * 16;
                xr[p] = *(const float4*)(X + (size_t)(row0 + r) * DMODEL + k0 + lc);
            }
#pragma unroll
            for (int p = 0; p < 4; ++p) {
                int idx = tid + p * 256;
                cp_async16(ws_u32 + (uint32_t)(nxt * 4096 + idx * 4) * 4,
                           Wt2 + (c + 1) * 4096 + idx * 4);
            }
            cp_commit();
        }

        // compute: 8 k-steps x 4 n-tiles; b-frags are single LDS.64
#pragma unroll
        for (int kk = 0; kk < 8; ++kk) {
            int r = 16 * wr + g;
            unsigned a0 = Xc[r * XS + kk * 8 + m];
            unsigned a1 = Xc[(r + 8) * XS + kk * 8 + m];
            unsigned a2 = Xc[r * XS + kk * 8 + m + 4];
            unsigned a3 = Xc[(r + 8) * XS + kk * 8 + m + 4];
            const unsigned* Wrow = Wc + (kk * 4 + m) * 128;
#pragma unroll
            for (int n = 0; n < 4; ++n) {
                int colp = (cb + 8 * n) & 63;
                uint2 wb = *(const uint2*)&Wrow[2 * colp];
                mma8(acc[n], a0, a1, a2, a3, wb.x, wb.y);
            }
        }

        if (has_next) {
            unsigned* Xn = Xs + nxt * 64 * XS;
#pragma unroll
            for (int p = 0; p < 4; ++p) {
                int r = lr + p * 16;
                *(uint4*)&Xn[r * XS + lc] =
                    make_uint4(f2tf(xr[p].x), f2tf(xr[p].y), f2tf(xr[p].z), f2tf(xr[p].w));
            }
        }
        cp_wait0();
        __syncthreads();
        cur = nxt;
    }

    // epilogue
#pragma unroll
    for (int n = 0; n < 4; ++n) {
        int col = 32 * wc + n * 8 + 2 * m;
        float bj0 = Bb[col];
        float bj1 = Bb[col + 1];
        int r = row0 + 16 * wr + g;
        unsigned o00 = f2tf((acc[n].x + bj0) * oscale);
        unsigned o01 = f2tf((acc[n].y + bj1) * oscale);
        unsigned o10 = f2tf((acc[n].z + bj0) * oscale);
        unsigned o11 = f2tf((acc[n].w + bj1) * oscale);
        if (sel == 2) {
            // pair-packed V scatter
#pragma unroll
            for (int e = 0; e < 4; ++e) {
                int R  = (e & 2) ? (r + 8) : r;
                int cc = col + (e & 1);
                unsigned val = (e == 0) ? o00 : (e == 1) ? o01 : (e == 2) ? o10 : o11;
                int rp   = ((R >> 3) << 2) | (R & 3);
                int slot = (R >> 2) & 1;
                int colp = (cc + 4 * (R & 3)) & 63;
                g_v2[rp * 128 + 2 * colp + slot] = val;
            }
        } else {
            unsigned* __restrict__ Y = g_proj[sel];
            int base = 32 * wc + n * 8;
            int pos0 = (m < 2) ? 4 * m : 4 * m - 7;   // col-pair permutation of j=2m
            Y[(size_t)r * DK + base + pos0]           = o00;
            Y[(size_t)r * DK + base + pos0 + 2]       = o01;
            Y[(size_t)(r + 8) * DK + base + pos0]     = o10;
            Y[(size_t)(r + 8) * DK + base + pos0 + 2] = o11;
        }
    }
}

// ===========================================================================
// Fused attention: Q/K col-pair-permuted tf32 bits; V pair-packed.
// cp.async K/V, double-buffered, 512 thr.  All MMA b-frags are LDS.64.
// KSS=72: frag start bank = (8g+2m) mod 32 -> conflict-free LDS.64.
// ===========================================================================
#define KSS 72

__global__ __launch_bounds__(512, 1) void attn_kernel(float* __restrict__ out)
{
    unsigned* Ks = dyn_smem;                 // 2 * 64*72 = 9216 words
    unsigned* Vs = dyn_smem + 2 * 64 * KSS;  // 2 * 4096 = 8192 words (pair-packed)
    float* den = (float*)(dyn_smem + 2 * 64 * KSS + 2 * 4096);
    float* Of0 = (float*)Ks;                 // 4096 <= 9216
    float* Of1 = (float*)Vs;                 // 4096 <= 8192
    const uint32_t ks_u32 = smem_u32(Ks);
    const uint32_t vs_u32 = smem_u32(Vs);

    const int tid  = threadIdx.x;
    const int wid  = tid >> 5;
    const int lane = tid & 31;
    const int g    = lane >> 2;
    const int m    = lane & 3;
    const int wr   = wid & 3;
    const int wkc  = wid >> 2;

    const int b  = blockIdx.y;
    const int q0 = blockIdx.x * 64;

    const unsigned* __restrict__ Qg = g_proj[0] + ((size_t)b * SEQ + q0) * DK;
    const unsigned* __restrict__ Kg = g_proj[1] + (size_t)b * SEQ * DK;

    const int lr = tid >> 4;
    const int lc = (tid & 15) * 4;

    if (tid < 64) den[tid] = 0.f;

    // ---- stage Q through Ks buffer 0; a-frag pairs load as LDS.64 ----------
#pragma unroll
    for (int p = 0; p < 2; ++p) {
        int r = lr + p * 32;
        *(uint4*)&Ks[r * KSS + lc] = *(const uint4*)(Qg + (size_t)r * DK + lc);
    }
    __syncthreads();

    unsigned qa[8][4];
#pragma unroll
    for (int kk = 0; kk < 8; ++kk) {
        int r = 16 * wr + g;
        uint2 qlo = *(const uint2*)&Ks[r * KSS + kk * 8 + 2 * m];
        uint2 qhi = *(const uint2*)&Ks[(r + 8) * KSS + kk * 8 + 2 * m];
        qa[kk][0] = qlo.x;
        qa[kk][2] = qlo.y;
        qa[kk][1] = qhi.x;
        qa[kk][3] = qhi.y;
    }
    __syncthreads();

    float4 oacc[8];
#pragma unroll
    for (int n = 0; n < 8; ++n) {
        oacc[n] = make_float4(0.f, 0.f, 0.f, 0.f);
    }
    float dp0 = 0.f;
    float dp1 = 0.f;

    const int s0 = (lane & ~3) | (m >> 1);
    const int s1 = s0 + 2;
    const bool od = (m & 1);

    // ---- preload tile 0 ----
#pragma unroll
    for (int p = 0; p < 2; ++p) {
        int r = lr + p * 32;
        cp_async16(ks_u32 + (uint32_t)(r * KSS + lc) * 4, Kg + (size_t)r * DK + lc);
    }
    {
        const unsigned* Vsrc = g_v2 + ((size_t)b * (SEQ / 2)) * 128;
#pragma unroll
        for (int p = 0; p < 2; ++p) {
            int idx = tid + p * 512;            // 0..1023 uint4 chunks
            cp_async16(vs_u32 + (uint32_t)(idx * 4) * 4, Vsrc + idx * 4);
        }
    }
    cp_commit();

    const int vcb = g + 4 * m;   // rotated base col for V b-frags

    int cur = 0;
    for (int t = 0; t < SEQ / 64; ++t) {
        cp_wait0();
        __syncthreads();

        const unsigned* Kc = Ks + cur * 64 * KSS;
        const unsigned* Vc = Vs + cur * 4096;
        const int nxt = cur ^ 1;

        if (t + 1 < SEQ / 64) {
            int n1 = (t + 1) * 64;
#pragma unroll
            for (int p = 0; p < 2; ++p) {
                int r = lr + p * 32;
                cp_async16(ks_u32 + (uint32_t)(nxt * 64 * KSS + r * KSS + lc) * 4,
                           Kg + (size_t)(n1 + r) * DK + lc);
            }
            const unsigned* Vsrc = g_v2 + ((size_t)b * (SEQ / 2) + (size_t)(t + 1) * 32) * 128;
#pragma unroll
            for (int p = 0; p < 2; ++p) {
                int idx = tid + p * 512;
                cp_async16(vs_u32 + (uint32_t)(nxt * 4096 + idx * 4) * 4, Vsrc + idx * 4);
            }
            cp_commit();
        }

        // ---- S = Q K^T ----
        float4 sa[2];
        sa[0] = make_float4(0.f, 0.f, 0.f, 0.f);
        sa[1] = make_float4(0.f, 0.f, 0.f, 0.f);
#pragma unroll
        for (int kk = 0; kk < 8; ++kk) {
#pragma unroll
            for (int n = 0; n < 2; ++n) {
                int krow = 16 * wkc + n * 8 + g;
                uint2 kb = *(const uint2*)&Kc[krow * KSS + kk * 8 + 2 * m];
                mma8(sa[n], qa[kk][0], qa[kk][1], qa[kk][2], qa[kk][3], kb.x, kb.y);
            }
        }

        // ---- exp ----
#pragma unroll
        for (int n = 0; n < 2; ++n) {
            float e0 = __uint_as_float(f2tf(__expf(sa[n].x)));
            float e1 = __uint_as_float(f2tf(__expf(sa[n].y)));
            float e2 = __uint_as_float(f2tf(__expf(sa[n].z)));
            float e3 = __uint_as_float(f2tf(__expf(sa[n].w)));
            dp0 += e0 + e1;
            dp1 += e2 + e3;
            sa[n] = make_float4(e0, e1, e2, e3);
        }

        // ---- O += E V (pair-packed V: LDS.64 b-frags) ----
#pragma unroll
        for (int kk2 = 0; kk2 < 2; ++kk2) {
            float c0 = sa[kk2].x;
            float c1 = sa[kk2].y;
            float c2 = sa[kk2].z;
            float c3 = sa[kk2].w;
            float x00 = __shfl_sync(0xffffffffu, c0, s0);
            float x01 = __shfl_sync(0xffffffffu, c1, s0);
            float x10 = __shfl_sync(0xffffffffu, c2, s0);
            float x11 = __shfl_sync(0xffffffffu, c3, s0);
            float x20 = __shfl_sync(0xffffffffu, c0, s1);
            float x21 = __shfl_sync(0xffffffffu, c1, s1);
            float x30 = __shfl_sync(0xffffffffu, c2, s1);
            float x31 = __shfl_sync(0xffffffffu, c3, s1);
            unsigned a0 = __float_as_uint(od ? x01 : x00);
            unsigned a1 = __float_as_uint(od ? x11 : x10);
            unsigned a2 = __float_as_uint(od ? x21 : x20);
            unsigned a3 = __float_as_uint(od ? x31 : x30);
            const unsigned* Vrow = Vc + ((2 * wkc + kk2) * 4 + m) * 128;
#pragma unroll
            for (int n2 = 0; n2 < 8; ++n2) {
                int colp = (vcb + 8 * n2) & 63;
                uint2 vb = *(const uint2*)&Vrow[2 * colp];
                mma8(oacc[n2], a0, a1, a2, a3, vb.x, vb.y);
            }
        }

        cur = nxt;
    }
    __syncthreads();

    // ---- denominator ----
    dp0 += __shfl_xor_sync(0xffffffffu, dp0, 1);
    dp0 += __shfl_xor_sync(0xffffffffu, dp0, 2);
    dp1 += __shfl_xor_sync(0xffffffffu, dp1, 1);
    dp1 += __shfl_xor_sync(0xffffffffu, dp1, 2);
    if (m == 0) {
        atomicAdd(&den[16 * wr + g], dp0);
        atomicAdd(&den[16 * wr + g + 8], dp1);
    }

    // ---- O reduction ----
    if (wkc == 0) {
#pragma unroll
        for (int n2 = 0; n2 < 8; ++n2) {
            int r = 16 * wr + g;
            int col = n2 * 8 + 2 * m;
            *(float2*)&Of0[r * 64 + col]       = make_float2(oacc[n2].x, oacc[n2].y);
            *(float2*)&Of0[(r + 8) * 64 + col] = make_float2(oacc[n2].z, oacc[n2].w);
        }
    } else if (wkc == 1) {
#pragma unroll
        for (int n2 = 0; n2 < 8; ++n2) {
            int r = 16 * wr + g;
            int col = n2 * 8 + 2 * m;
            *(float2*)&Of1[r * 64 + col]       = make_float2(oacc[n2].x, oacc[n2].y);
            *(float2*)&Of1[(r + 8) * 64 + col] = make_float2(oacc[n2].z, oacc[n2].w);
        }
    }
    __syncthreads();
    if (wkc == 2) {
#pragma unroll
        for (int n2 = 0; n2 < 8; ++n2) {
            int r = 16 * wr + g;
            int col = n2 * 8 + 2 * m;
            float2 p0 = *(float2*)&Of0[r * 64 + col];
            float2 p1 = *(float2*)&Of0[(r + 8) * 64 + col];
            p0.x += oacc[n2].x; p0.y += oacc[n2].y;
            p1.x += oacc[n2].z; p1.y += oacc[n2].w;
            *(float2*)&Of0[r * 64 + col]       = p0;
            *(float2*)&Of0[(r + 8) * 64 + col] = p1;
        }
    } else if (wkc == 3) {
#pragma unroll
        for (int n2 = 0; n2 < 8; ++n2) {
            int r = 16 * wr + g;
            int col = n2 * 8 + 2 * m;
            float2 p0 = *(float2*)&Of1[r * 64 + col];
            float2 p1 = *(float2*)&Of1[(r + 8) * 64 + col];
            p0.x += oacc[n2].x; p0.y += oacc[n2].y;
            p1.x += oacc[n2].z; p1.y += oacc[n2].w;
            *(float2*)&Of1[r * 64 + col]       = p0;
            *(float2*)&Of1[(r + 8) * 64 + col] = p1;
        }
    }
    __syncthreads();

    // ---- normalize + writeout ----
    float* __restrict__ Og = out + ((size_t)b * SEQ + q0) * DK;
#pragma unroll
    for (int i = 0; i < 2; ++i) {
        int e4 = tid + i * 512;
        int row = e4 >> 4;
        float inv = 1.0f / den[row];
        float4 oa = ((const float4*)Of0)[e4];
        float4 ob = ((const float4*)Of1)[e4];
        float4 o;
        o.x = (oa.x + ob.x) * inv;
        o.y = (oa.y + ob.y) * inv;
        o.z = (oa.z + ob.z) * inv;
        o.w = (oa.w + ob.w) * inv;
        ((float4*)Og)[e4] = o;
    }
}

// ---------------------------------------------------------------------------
extern "C" void kernel_launch(void* const* d_in, const int* in_sizes, int n_in,
                              void* d_out, int out_size)
{
    const float* q  = (const float*)d_in[0];
    const float* k  = (const float*)d_in[1];
    const float* v  = (const float*)d_in[2];
    const float* Wq = (const float*)d_in[3];
    const float* bq = (const float*)d_in[4];
    const float* Wk = (const float*)d_in[5];
    const float* bk = (const float*)d_in[6];
    const float* Wv = (const float*)d_in[7];
    const float* bv = (const float*)d_in[8];
    float* out = (float*)d_out;

    const int psmem = (2 * 64 * XS + 2 * 4096) * 4;            // 67584 B
    const int asmem = (2 * 64 * KSS + 2 * 4096 + 64) * 4;      // 69888 B
    cudaFuncSetAttribute(proj_kernel, cudaFuncAttributeMaxDynamicSharedMemorySize, psmem);
    cudaFuncSetAttribute(attn_kernel, cudaFuncAttributeMaxDynamicSharedMemorySize, asmem);

    dim3 wgrid(64, 1, 3);
    wprep_kernel<<<wgrid, 256>>>(Wq, Wk, Wv);

    dim3 pgrid(BATCH * SEQ / 64, 1, 3);
    proj_kernel<<<pgrid, 256, psmem>>>(q, k, v, bq, bk, bv);

    dim3 agrid(SEQ / 64, BATCH);
    attn_kernel<<<agrid, 512, asmem>>>(out);
}